// round 1
// baseline (speedup 1.0000x reference)
#include <cuda_runtime.h>

// Problem constants
#define BATCH 16
#define CH    2048
#define HID   256
#define HW    1024

// Scratch (device globals are the sanctioned alloc-free scratch mechanism)
__device__ float g_Q[BATCH * HID * HW];          // 16 MiB
__device__ float g_K[BATCH * HID * HW];          // 16 MiB
__device__ float g_S[BATCH * HW * HW];           // 64 MiB (scores -> softmax probs)

// ---------------------------------------------------------------------------
// Copy query_features into first half of concat output (channels [0,2048))
// ---------------------------------------------------------------------------
__global__ void copy_first_half(const float* __restrict__ qf, float* __restrict__ out) {
    int idx = blockIdx.x * blockDim.x + threadIdx.x;        // float4 index
    const int perb = (CH * HW) / 4;                          // 524288 float4 per batch
    int b = idx / perb;
    int r = idx - b * perb;
    const float4* in4 = reinterpret_cast<const float4*>(qf);
    float4* out4 = reinterpret_cast<float4*>(out);
    out4[(size_t)b * (2 * CH * HW / 4) + r] = in4[idx];
}

// ---------------------------------------------------------------------------
// Shared inner product step for the 128x128 / BK=8 / 8x8-per-thread tiling
// ---------------------------------------------------------------------------
__device__ __forceinline__ void mm_step(const float (&As)[8][128], const float (&Bs)[8][128],
                                        int tm, int tn, float (&acc)[8][8]) {
#pragma unroll
    for (int kk = 0; kk < 8; ++kk) {
        float4 a0 = *reinterpret_cast<const float4*>(&As[kk][tm]);
        float4 a1 = *reinterpret_cast<const float4*>(&As[kk][tm + 4]);
        float4 b0 = *reinterpret_cast<const float4*>(&Bs[kk][tn]);
        float4 b1 = *reinterpret_cast<const float4*>(&Bs[kk][tn + 4]);
        float ar[8] = {a0.x, a0.y, a0.z, a0.w, a1.x, a1.y, a1.z, a1.w};
        float br[8] = {b0.x, b0.y, b0.z, b0.w, b1.x, b1.y, b1.z, b1.w};
#pragma unroll
        for (int i = 0; i < 8; ++i)
#pragma unroll
            for (int j = 0; j < 8; ++j)
                acc[i][j] = fmaf(ar[i], br[j], acc[i][j]);
    }
}

// ---------------------------------------------------------------------------
// Q/K projection: Out[b,o,hw] = bias[o] + sum_c W[o,c] * X[b,c,hw]
// M=256 (o), N=1024 (hw), K=2048 (c)
// ---------------------------------------------------------------------------
__global__ void __launch_bounds__(256) gemm_qk_kernel(const float* __restrict__ Wm,
                                                      const float* __restrict__ X,
                                                      const float* __restrict__ bias,
                                                      int which) {
    float* Out = which ? g_K : g_Q;
    const int N = HW, K = CH;
    int b = blockIdx.z;
    const float* Xb = X + (size_t)b * K * N;
    float* Cb = Out + (size_t)b * HID * N;
    int bm = blockIdx.y * 128;
    int bn = blockIdx.x * 128;
    __shared__ float As[8][128];
    __shared__ float Bs[8][128];
    int tid = threadIdx.x;
    int tm = (tid >> 4) << 3;
    int tn = (tid & 15) << 3;
    float acc[8][8];
#pragma unroll
    for (int i = 0; i < 8; ++i)
#pragma unroll
        for (int j = 0; j < 8; ++j) acc[i][j] = 0.0f;

    int ar_ = tid >> 1, ac_ = (tid & 1) * 4;    // A tile: 128 rows x 8 k, transpose into As
    int br_ = tid >> 5, bc_ = (tid & 31) * 4;   // B tile: 8 k x 128 n, coalesced

    for (int k0 = 0; k0 < K; k0 += 8) {
        float4 av = *reinterpret_cast<const float4*>(Wm + (size_t)(bm + ar_) * K + k0 + ac_);
        As[ac_ + 0][ar_] = av.x;
        As[ac_ + 1][ar_] = av.y;
        As[ac_ + 2][ar_] = av.z;
        As[ac_ + 3][ar_] = av.w;
        *reinterpret_cast<float4*>(&Bs[br_][bc_]) =
            *reinterpret_cast<const float4*>(Xb + (size_t)(k0 + br_) * N + bn + bc_);
        __syncthreads();
        mm_step(As, Bs, tm, tn, acc);
        __syncthreads();
    }
#pragma unroll
    for (int i = 0; i < 8; ++i) {
        float bv = bias[bm + tm + i];
        float4 o0 = {acc[i][0] + bv, acc[i][1] + bv, acc[i][2] + bv, acc[i][3] + bv};
        float4 o1 = {acc[i][4] + bv, acc[i][5] + bv, acc[i][6] + bv, acc[i][7] + bv};
        float* dst = Cb + (size_t)(bm + tm + i) * N + bn + tn;
        *reinterpret_cast<float4*>(dst) = o0;
        *reinterpret_cast<float4*>(dst + 4) = o1;
    }
}

// ---------------------------------------------------------------------------
// Scores: S[b,q,k] = sum_o Q[b,o,q] * K[b,o,k]   (both operands K-major)
// M=1024 (q), N=1024 (k), reduction = 256 (o)
// ---------------------------------------------------------------------------
__global__ void __launch_bounds__(256) gemm_scores_kernel() {
    const int N = HW, Kd = HID;
    int b = blockIdx.z;
    const float* Qb = g_Q + (size_t)b * Kd * N;
    const float* Kb = g_K + (size_t)b * Kd * N;
    float* Sb = g_S + (size_t)b * N * N;
    int bm = blockIdx.y * 128;
    int bn = blockIdx.x * 128;
    __shared__ float As[8][128];
    __shared__ float Bs[8][128];
    int tid = threadIdx.x;
    int tm = (tid >> 4) << 3;
    int tn = (tid & 15) << 3;
    float acc[8][8];
#pragma unroll
    for (int i = 0; i < 8; ++i)
#pragma unroll
        for (int j = 0; j < 8; ++j) acc[i][j] = 0.0f;

    int lk = tid >> 5;           // 0..7
    int lm = (tid & 31) * 4;     // 0..124  (coalesced 512B rows)

    for (int k0 = 0; k0 < Kd; k0 += 8) {
        *reinterpret_cast<float4*>(&As[lk][lm]) =
            *reinterpret_cast<const float4*>(Qb + (size_t)(k0 + lk) * N + bm + lm);
        *reinterpret_cast<float4*>(&Bs[lk][lm]) =
            *reinterpret_cast<const float4*>(Kb + (size_t)(k0 + lk) * N + bn + lm);
        __syncthreads();
        mm_step(As, Bs, tm, tn, acc);
        __syncthreads();
    }
#pragma unroll
    for (int i = 0; i < 8; ++i) {
        float4 o0 = {acc[i][0], acc[i][1], acc[i][2], acc[i][3]};
        float4 o1 = {acc[i][4], acc[i][5], acc[i][6], acc[i][7]};
        float* dst = Sb + (size_t)(bm + tm + i) * N + bn + tn;
        *reinterpret_cast<float4*>(dst) = o0;
        *reinterpret_cast<float4*>(dst + 4) = o1;
    }
}

// ---------------------------------------------------------------------------
// Row softmax over 1024 entries; one 256-thread block per row. In-place on g_S.
// ---------------------------------------------------------------------------
__global__ void softmax_rows() {
    int row = blockIdx.x;
    float* r = g_S + (size_t)row * HW;
    int tid = threadIdx.x;
    __shared__ float red[8];

    float4 v = *reinterpret_cast<float4*>(r + tid * 4);
    float m = fmaxf(fmaxf(v.x, v.y), fmaxf(v.z, v.w));
#pragma unroll
    for (int off = 16; off; off >>= 1) m = fmaxf(m, __shfl_xor_sync(0xffffffffu, m, off));
    if ((tid & 31) == 0) red[tid >> 5] = m;
    __syncthreads();
    float rowmax = red[0];
#pragma unroll
    for (int i = 1; i < 8; ++i) rowmax = fmaxf(rowmax, red[i]);

    v.x = __expf(v.x - rowmax);
    v.y = __expf(v.y - rowmax);
    v.z = __expf(v.z - rowmax);
    v.w = __expf(v.w - rowmax);
    float s = v.x + v.y + v.z + v.w;
#pragma unroll
    for (int off = 16; off; off >>= 1) s += __shfl_xor_sync(0xffffffffu, s, off);
    __syncthreads();                       // everyone done reading red[] for max
    if ((tid & 31) == 0) red[tid >> 5] = s;
    __syncthreads();
    float tot = red[0];
#pragma unroll
    for (int i = 1; i < 8; ++i) tot += red[i];
    float inv = 1.0f / tot;

    v.x *= inv; v.y *= inv; v.z *= inv; v.w *= inv;
    *reinterpret_cast<float4*>(r + tid * 4) = v;
}

// ---------------------------------------------------------------------------
// aligned[b,c,q] = sum_k P[b,q,k] * V[b,c,k], written directly into the second
// half of the concat output (channels [2048,4096)).
// M=2048 (c), N=1024 (q), reduction = 1024 (k)
// ---------------------------------------------------------------------------
__global__ void __launch_bounds__(256) gemm_av_kernel(const float* __restrict__ Vfull,
                                                      float* __restrict__ out) {
    const int Kd = HW;
    int b = blockIdx.z;
    const float* Vb = Vfull + (size_t)b * CH * Kd;
    const float* Pb = g_S + (size_t)b * HW * Kd;
    float* Ob = out + (size_t)b * (2 * CH * HW) + (size_t)CH * HW;
    int bm = blockIdx.y * 128;   // c
    int bn = blockIdx.x * 128;   // q
    __shared__ float As[8][128];
    __shared__ float Bs[8][128];
    int tid = threadIdx.x;
    int tm = (tid >> 4) << 3;
    int tn = (tid & 15) << 3;
    float acc[8][8];
#pragma unroll
    for (int i = 0; i < 8; ++i)
#pragma unroll
        for (int j = 0; j < 8; ++j) acc[i][j] = 0.0f;

    int r_ = tid >> 1, c_ = (tid & 1) * 4;   // both operands are row-major over k

    for (int k0 = 0; k0 < Kd; k0 += 8) {
        float4 av = *reinterpret_cast<const float4*>(Vb + (size_t)(bm + r_) * Kd + k0 + c_);
        As[c_ + 0][r_] = av.x;
        As[c_ + 1][r_] = av.y;
        As[c_ + 2][r_] = av.z;
        As[c_ + 3][r_] = av.w;
        float4 bv = *reinterpret_cast<const float4*>(Pb + (size_t)(bn + r_) * Kd + k0 + c_);
        Bs[c_ + 0][r_] = bv.x;
        Bs[c_ + 1][r_] = bv.y;
        Bs[c_ + 2][r_] = bv.z;
        Bs[c_ + 3][r_] = bv.w;
        __syncthreads();
        mm_step(As, Bs, tm, tn, acc);
        __syncthreads();
    }
#pragma unroll
    for (int i = 0; i < 8; ++i) {
        float4 o0 = {acc[i][0], acc[i][1], acc[i][2], acc[i][3]};
        float4 o1 = {acc[i][4], acc[i][5], acc[i][6], acc[i][7]};
        float* dst = Ob + (size_t)(bm + tm + i) * HW + bn + tn;
        *reinterpret_cast<float4*>(dst) = o0;
        *reinterpret_cast<float4*>(dst + 4) = o1;
    }
}

// ---------------------------------------------------------------------------
extern "C" void kernel_launch(void* const* d_in, const int* in_sizes, int n_in,
                              void* d_out, int out_size) {
    const float* qf   = (const float*)d_in[0];   // (16, 2048, 32, 32)
    const float* pf   = (const float*)d_in[1];   // (16, 2048, 32, 32)
    const float* Wm   = (const float*)d_in[2];   // (256, 2048)
    const float* bias = (const float*)d_in[3];   // (256,)
    float* out = (float*)d_out;                  // (16, 4096, 32, 32)

    copy_first_half<<<(BATCH * CH * HW / 4) / 256, 256>>>(qf, out);

    dim3 gqk(HW / 128, HID / 128, BATCH);        // (8, 2, 16)
    gemm_qk_kernel<<<gqk, 256>>>(Wm, qf, bias, 0);
    gemm_qk_kernel<<<gqk, 256>>>(Wm, pf, bias, 1);

    dim3 gs(HW / 128, HW / 128, BATCH);          // (8, 8, 16)
    gemm_scores_kernel<<<gs, 256>>>();

    softmax_rows<<<BATCH * HW, 256>>>();

    dim3 gav(HW / 128, CH / 128, BATCH);         // (8, 16, 16)
    gemm_av_kernel<<<gav, 256>>>(pf, out);
}

// round 3
// speedup vs baseline: 2.7562x; 2.7562x over previous
#include <cuda_runtime.h>
#include <cstdint>

#define BATCH 16
#define CH    2048
#define HID   256
#define HW    1024

// Scratch
__device__ float g_Qt[BATCH * HW * HID];         // 16 MiB  Qt[b][q][o]
__device__ float g_Kt[BATCH * HW * HID];         // 16 MiB  Kt[b][k2][o]
__device__ float g_S [BATCH * HW * HW];          // 64 MiB  scores -> probs

// ===========================================================================
// mma.sync / ldmatrix helpers (base-target sm_80+ instructions only)
// ===========================================================================
__device__ __forceinline__ uint32_t smem_u32(const void* p) {
    uint32_t a;
    asm("{ .reg .u64 t; cvta.to.shared.u64 t, %1; cvt.u32.u64 %0, t; }" : "=r"(a) : "l"(p));
    return a;
}
__device__ __forceinline__ void ldsm4(uint32_t (&r)[4], uint32_t addr) {
    asm volatile("ldmatrix.sync.aligned.m8n8.x4.shared.b16 {%0,%1,%2,%3}, [%4];"
                 : "=r"(r[0]), "=r"(r[1]), "=r"(r[2]), "=r"(r[3]) : "r"(addr));
}
__device__ __forceinline__ void ldsm4t(uint32_t (&r)[4], uint32_t addr) {
    asm volatile("ldmatrix.sync.aligned.m8n8.x4.trans.shared.b16 {%0,%1,%2,%3}, [%4];"
                 : "=r"(r[0]), "=r"(r[1]), "=r"(r[2]), "=r"(r[3]) : "r"(addr));
}
__device__ __forceinline__ void mma_bf16(float (&d)[4], const uint32_t (&a)[4],
                                         uint32_t b0, uint32_t b1) {
    asm volatile("mma.sync.aligned.m16n8k16.row.col.f32.bf16.bf16.f32 "
                 "{%0,%1,%2,%3}, {%4,%5,%6,%7}, {%8,%9}, {%0,%1,%2,%3};"
                 : "+f"(d[0]), "+f"(d[1]), "+f"(d[2]), "+f"(d[3])
                 : "r"(a[0]), "r"(a[1]), "r"(a[2]), "r"(a[3]), "r"(b0), "r"(b1));
}
// Split two fp32 into packed bf16 hi-pair + lo-pair (word = {x1:hi16, x0:lo16})
__device__ __forceinline__ void split2(float x0, float x1, uint32_t& hi, uint32_t& lo) {
    uint32_t h;
    asm("cvt.rn.bf16x2.f32 %0, %1, %2;" : "=r"(h) : "f"(x1), "f"(x0));
    float h0 = __uint_as_float(h << 16);
    float h1 = __uint_as_float(h & 0xffff0000u);
    float l0 = x0 - h0, l1 = x1 - h1;
    uint32_t l;
    asm("cvt.rn.bf16x2.f32 %0, %1, %2;" : "=r"(l) : "f"(l1), "f"(l0));
    hi = h; lo = l;
}

// SMEM layout (bytes). Row strides chosen so every ldmatrix phase hits a
// perfect bank partition (80B: 20r mod 32 banks; 272B: 68r ≡ 4r mod 32).
#define A_RS   80      // normal A / B row stride ([m or n][k=32 bf16] + 16B pad)
#define A_RS_T 272     // trans A row stride ([k][m=128 bf16] + 16B pad)
#define OFF_AHI 0
#define OFF_ALO 10240
#define OFF_BHI 20480
#define OFF_BLO 30720
#define OFF_BIAS 40960
#define SMEM_BYTES (OFF_BIAS + 512)

// ===========================================================================
// Generic 3-term split-bf16 GEMM
//   C[b][m][n] = sum_k A[m][k] * B[n][k]   (+ bias[n] if BIAS)
// TRANSA=1: A source stored [k][m] (row stride ldA over k-rows)
// Tiles: BM=128, BN=128, BK=32; 256 threads; warp tile 64x32 (2x4 warp grid).
// ===========================================================================
template <int TRANSA, int BIAS>
__global__ void __launch_bounds__(256)
mma3_kernel(const float* __restrict__ A, const float* __restrict__ B,
            const float* __restrict__ bias, float* __restrict__ C, int K,
            int ldA, int ldB, int ldC,
            unsigned long long sA, unsigned long long sB, unsigned long long sC) {
    __shared__ __align__(1024) char sm[SMEM_BYTES];
    const uint32_t sbase = smem_u32(sm);
    const int tid = threadIdx.x;
    const int lane = tid & 31;
    const int wid = tid >> 5;
    const int wm = (wid & 1) * 64;          // warp m offset within CTA tile
    const int wn = (wid >> 1) * 32;         // warp n offset

    const int m0 = blockIdx.y * 128;
    const int n0 = blockIdx.x * 128;
    const int b  = blockIdx.z;

    const float* Ab = TRANSA ? (A + (size_t)b * sA + m0)
                             : (A + (size_t)b * sA + (size_t)m0 * ldA);
    const float* Bb = B + (size_t)b * sB + (size_t)n0 * ldB;

    float* biasS = reinterpret_cast<float*>(sm + OFF_BIAS);
    if (BIAS && tid < 128) biasS[tid] = bias[n0 + tid];

    float acc[4][4][4];
#pragma unroll
    for (int i = 0; i < 4; ++i)
#pragma unroll
        for (int j = 0; j < 4; ++j)
#pragma unroll
            for (int v = 0; v < 4; ++v) acc[i][j][v] = 0.0f;

    // ldmatrix lane-address components (constant over loop)
    const int aM_row = lane & 15;                            // normal A
    const int aM_col = (lane & 16) ? 8 : 0;
    const int aT_k   = (lane & 7) + ((lane & 16) ? 8 : 0);   // trans A
    const int aT_m   = (lane & 8) ? 8 : 0;
    const int bN_row = (lane & 7) + ((lane & 16) ? 8 : 0);   // B
    const int bN_col = (lane & 8) ? 8 : 0;

    const int nIter = K >> 5;
    float4 pa[4], pb[4];

    // ---- prefetch chunk 0
#pragma unroll
    for (int p = 0; p < 4; ++p) {
        int i = p * 256 + tid;
        if (TRANSA) {
            int kr = i >> 5, m4 = (i & 31) * 4;
            pa[p] = *reinterpret_cast<const float4*>(Ab + (size_t)kr * ldA + m4);
        } else {
            int row = i >> 3, k4 = (i & 7) * 4;
            pa[p] = *reinterpret_cast<const float4*>(Ab + (size_t)row * ldA + k4);
        }
        int row = i >> 3, k4 = (i & 7) * 4;
        pb[p] = *reinterpret_cast<const float4*>(Bb + (size_t)row * ldB + k4);
    }

    for (int ch = 0; ch < nIter; ++ch) {
        __syncthreads();   // previous tile fully consumed
        // ---- store prefetched chunk (split hi/lo)
#pragma unroll
        for (int p = 0; p < 4; ++p) {
            int i = p * 256 + tid;
            uint32_t h0, l0, h1, l1;
            if (TRANSA) {
                int kr = i >> 5, m4 = (i & 31) * 4;
                split2(pa[p].x, pa[p].y, h0, l0);
                split2(pa[p].z, pa[p].w, h1, l1);
                uint32_t off = (uint32_t)kr * A_RS_T + m4 * 2;
                *reinterpret_cast<uint2*>(sm + OFF_AHI + off) = make_uint2(h0, h1);
                *reinterpret_cast<uint2*>(sm + OFF_ALO + off) = make_uint2(l0, l1);
            } else {
                int row = i >> 3, k4 = (i & 7) * 4;
                split2(pa[p].x, pa[p].y, h0, l0);
                split2(pa[p].z, pa[p].w, h1, l1);
                uint32_t off = (uint32_t)row * A_RS + k4 * 2;
                *reinterpret_cast<uint2*>(sm + OFF_AHI + off) = make_uint2(h0, h1);
                *reinterpret_cast<uint2*>(sm + OFF_ALO + off) = make_uint2(l0, l1);
            }
            int row = i >> 3, k4 = (i & 7) * 4;
            split2(pb[p].x, pb[p].y, h0, l0);
            split2(pb[p].z, pb[p].w, h1, l1);
            uint32_t off = (uint32_t)row * A_RS + k4 * 2;
            *reinterpret_cast<uint2*>(sm + OFF_BHI + off) = make_uint2(h0, h1);
            *reinterpret_cast<uint2*>(sm + OFF_BLO + off) = make_uint2(l0, l1);
        }
        __syncthreads();

        // ---- prefetch next chunk (LDG latency hidden under mma)
        if (ch + 1 < nIter) {
            const int k0 = (ch + 1) * 32;
#pragma unroll
            for (int p = 0; p < 4; ++p) {
                int i = p * 256 + tid;
                if (TRANSA) {
                    int kr = i >> 5, m4 = (i & 31) * 4;
                    pa[p] = *reinterpret_cast<const float4*>(Ab + (size_t)(k0 + kr) * ldA + m4);
                } else {
                    int row = i >> 3, k4 = (i & 7) * 4;
                    pa[p] = *reinterpret_cast<const float4*>(Ab + (size_t)row * ldA + k0 + k4);
                }
                int row = i >> 3, k4 = (i & 7) * 4;
                pb[p] = *reinterpret_cast<const float4*>(Bb + (size_t)row * ldB + k0 + k4);
            }
        }

        // ---- mma over current tile: 2 k-steps x 3 terms x 16 mma
#pragma unroll
        for (int ks = 0; ks < 2; ++ks) {
            uint32_t Ah[4][4], Al[4][4], Bh[2][4], Bl[2][4];
#pragma unroll
            for (int mi = 0; mi < 4; ++mi) {
                uint32_t offH, offL;
                if (TRANSA) {
                    uint32_t o = (uint32_t)(ks * 16 + aT_k) * A_RS_T +
                                 (uint32_t)(wm + mi * 16 + aT_m) * 2;
                    offH = sbase + OFF_AHI + o;
                    offL = sbase + OFF_ALO + o;
                    ldsm4t(Ah[mi], offH);
                    ldsm4t(Al[mi], offL);
                } else {
                    uint32_t o = (uint32_t)(wm + mi * 16 + aM_row) * A_RS +
                                 (uint32_t)(ks * 16 + aM_col) * 2;
                    offH = sbase + OFF_AHI + o;
                    offL = sbase + OFF_ALO + o;
                    ldsm4(Ah[mi], offH);
                    ldsm4(Al[mi], offL);
                }
            }
#pragma unroll
            for (int j = 0; j < 2; ++j) {
                uint32_t o = (uint32_t)(wn + j * 16 + bN_row) * A_RS +
                             (uint32_t)(ks * 16 + bN_col) * 2;
                ldsm4(Bh[j], sbase + OFF_BHI + o);
                ldsm4(Bl[j], sbase + OFF_BLO + o);
            }
#pragma unroll
            for (int mi = 0; mi < 4; ++mi)
#pragma unroll
                for (int nj = 0; nj < 4; ++nj) {
                    uint32_t bh0 = Bh[nj >> 1][(nj & 1) * 2];
                    uint32_t bh1 = Bh[nj >> 1][(nj & 1) * 2 + 1];
                    uint32_t bl0 = Bl[nj >> 1][(nj & 1) * 2];
                    uint32_t bl1 = Bl[nj >> 1][(nj & 1) * 2 + 1];
                    mma_bf16(acc[mi][nj], Ah[mi], bh0, bh1);
                    mma_bf16(acc[mi][nj], Ah[mi], bl0, bl1);
                    mma_bf16(acc[mi][nj], Al[mi], bh0, bh1);
                }
        }
    }

    // ---- epilogue
    float* Cb = C + (size_t)b * sC + (size_t)m0 * ldC + n0;
    const int q4 = lane >> 2, t4 = lane & 3;
#pragma unroll
    for (int mi = 0; mi < 4; ++mi) {
#pragma unroll
        for (int nj = 0; nj < 4; ++nj) {
            int r0 = wm + mi * 16 + q4;
            int c0 = wn + nj * 8 + t4 * 2;
            float b0 = BIAS ? biasS[c0] : 0.0f;
            float b1 = BIAS ? biasS[c0 + 1] : 0.0f;
            float2 v0 = {acc[mi][nj][0] + b0, acc[mi][nj][1] + b1};
            float2 v1 = {acc[mi][nj][2] + b0, acc[mi][nj][3] + b1};
            *reinterpret_cast<float2*>(Cb + (size_t)r0 * ldC + c0) = v0;
            *reinterpret_cast<float2*>(Cb + (size_t)(r0 + 8) * ldC + c0) = v1;
        }
    }
}

// ===========================================================================
// Copy query_features into concat first half
// ===========================================================================
__global__ void copy_first_half(const float* __restrict__ qf, float* __restrict__ out) {
    int idx = blockIdx.x * blockDim.x + threadIdx.x;
    const int perb = (CH * HW) / 4;
    int b = idx / perb;
    int r = idx - b * perb;
    reinterpret_cast<float4*>(out)[(size_t)b * (2 * CH * HW / 4) + r] =
        reinterpret_cast<const float4*>(qf)[idx];
}

// ===========================================================================
// Row softmax over 1024 entries, in place on g_S
// ===========================================================================
__global__ void softmax_rows() {
    int row = blockIdx.x;
    float* r = g_S + (size_t)row * HW;
    int tid = threadIdx.x;
    __shared__ float red[8];

    float4 v = *reinterpret_cast<float4*>(r + tid * 4);
    float m = fmaxf(fmaxf(v.x, v.y), fmaxf(v.z, v.w));
#pragma unroll
    for (int off = 16; off; off >>= 1) m = fmaxf(m, __shfl_xor_sync(0xffffffffu, m, off));
    if ((tid & 31) == 0) red[tid >> 5] = m;
    __syncthreads();
    float rowmax = red[0];
#pragma unroll
    for (int i = 1; i < 8; ++i) rowmax = fmaxf(rowmax, red[i]);

    v.x = __expf(v.x - rowmax);
    v.y = __expf(v.y - rowmax);
    v.z = __expf(v.z - rowmax);
    v.w = __expf(v.w - rowmax);
    float s = v.x + v.y + v.z + v.w;
#pragma unroll
    for (int off = 16; off; off >>= 1) s += __shfl_xor_sync(0xffffffffu, s, off);
    __syncthreads();
    if ((tid & 31) == 0) red[tid >> 5] = s;
    __syncthreads();
    float tot = red[0];
#pragma unroll
    for (int i = 1; i < 8; ++i) tot += red[i];
    float inv = 1.0f / tot;

    v.x *= inv; v.y *= inv; v.z *= inv; v.w *= inv;
    *reinterpret_cast<float4*>(r + tid * 4) = v;
}

// ===========================================================================
extern "C" void kernel_launch(void* const* d_in, const int* in_sizes, int n_in,
                              void* d_out, int out_size) {
    const float* qf   = (const float*)d_in[0];   // (16, 2048, 32, 32)
    const float* pf   = (const float*)d_in[1];   // (16, 2048, 32, 32)
    const float* Wm   = (const float*)d_in[2];   // (256, 2048)
    const float* bias = (const float*)d_in[3];   // (256,)
    float* out = (float*)d_out;                  // (16, 4096, 32, 32)

    float *Qt, *Kt, *S;
    cudaGetSymbolAddress((void**)&Qt, g_Qt);
    cudaGetSymbolAddress((void**)&Kt, g_Kt);
    cudaGetSymbolAddress((void**)&S,  g_S);

    copy_first_half<<<(BATCH * CH * HW / 4) / 256, 256>>>(qf, out);

    // Qt[hw][o] = sum_c X[c][hw] * W[o][c]  — A=X trans-src, B=W, bias over n=o
    dim3 gqk(HID / 128, HW / 128, BATCH);        // (2, 8, 16)
    mma3_kernel<1, 1><<<gqk, 256>>>(qf, Wm, bias, Qt, CH, HW, CH, HID,
                                    (unsigned long long)CH * HW, 0ULL,
                                    (unsigned long long)HW * HID);
    mma3_kernel<1, 1><<<gqk, 256>>>(pf, Wm, bias, Kt, CH, HW, CH, HID,
                                    (unsigned long long)CH * HW, 0ULL,
                                    (unsigned long long)HW * HID);

    // S[q][k2] = sum_o Qt[q][o] * Kt[k2][o]
    dim3 gs(HW / 128, HW / 128, BATCH);          // (8, 8, 16)
    mma3_kernel<0, 0><<<gs, 256>>>(Qt, Kt, nullptr, S, HID, HID, HID, HW,
                                   (unsigned long long)HW * HID,
                                   (unsigned long long)HW * HID,
                                   (unsigned long long)HW * HW);

    softmax_rows<<<BATCH * HW, 256>>>();

    // out2[c][q] = sum_k2 V[c][k2] * P[q][k2]
    dim3 gav(HW / 128, CH / 128, BATCH);         // (8, 16, 16)
    mma3_kernel<0, 0><<<gav, 256>>>(pf, S, nullptr, out + (size_t)CH * HW, HW,
                                    HW, HW, HW,
                                    (unsigned long long)CH * HW,
                                    (unsigned long long)HW * HW,
                                    (unsigned long long)2 * CH * HW);
}

// round 4
// speedup vs baseline: 2.7969x; 1.0148x over previous
#include <cuda_runtime.h>
#include <cuda_bf16.h>
#include <cstdint>

#define BATCH 16
#define CH    2048
#define HID   256
#define HW    1024

// ---- pre-split operand storage (bf16 hi/lo) + fp32 scores ----
__device__ __align__(128) __nv_bfloat16 g_XqHi[BATCH*CH*HW], g_XqLo[BATCH*CH*HW];
__device__ __align__(128) __nv_bfloat16 g_XpHi[BATCH*CH*HW], g_XpLo[BATCH*CH*HW];
__device__ __align__(128) __nv_bfloat16 g_WHi [HID*CH],      g_WLo [HID*CH];
__device__ __align__(128) __nv_bfloat16 g_QHi [BATCH*HW*HID], g_QLo[BATCH*HW*HID];
__device__ __align__(128) __nv_bfloat16 g_KHi [BATCH*HW*HID], g_KLo[BATCH*HW*HID];
__device__ __align__(128) __nv_bfloat16 g_PHi [BATCH*HW*HW],  g_PLo[BATCH*HW*HW];
__device__ __align__(128) float         g_S  [BATCH*HW*HW];

// ===========================================================================
// Helpers (all base-target sm_80+ instructions)
// ===========================================================================
__device__ __forceinline__ uint32_t smem_u32(const void* p) {
    uint32_t a;
    asm("{ .reg .u64 t; cvta.to.shared.u64 t, %1; cvt.u32.u64 %0, t; }" : "=r"(a) : "l"(p));
    return a;
}
__device__ __forceinline__ void ldsm4(uint32_t (&r)[4], uint32_t addr) {
    asm volatile("ldmatrix.sync.aligned.m8n8.x4.shared.b16 {%0,%1,%2,%3}, [%4];"
                 : "=r"(r[0]), "=r"(r[1]), "=r"(r[2]), "=r"(r[3]) : "r"(addr));
}
__device__ __forceinline__ void ldsm4t(uint32_t (&r)[4], uint32_t addr) {
    asm volatile("ldmatrix.sync.aligned.m8n8.x4.trans.shared.b16 {%0,%1,%2,%3}, [%4];"
                 : "=r"(r[0]), "=r"(r[1]), "=r"(r[2]), "=r"(r[3]) : "r"(addr));
}
__device__ __forceinline__ void mma_bf16(float (&d)[4], const uint32_t (&a)[4],
                                         uint32_t b0, uint32_t b1) {
    asm volatile("mma.sync.aligned.m16n8k16.row.col.f32.bf16.bf16.f32 "
                 "{%0,%1,%2,%3}, {%4,%5,%6,%7}, {%8,%9}, {%0,%1,%2,%3};"
                 : "+f"(d[0]), "+f"(d[1]), "+f"(d[2]), "+f"(d[3])
                 : "r"(a[0]), "r"(a[1]), "r"(a[2]), "r"(a[3]), "r"(b0), "r"(b1));
}
__device__ __forceinline__ void split2(float x0, float x1, uint32_t& hi, uint32_t& lo) {
    uint32_t h;
    asm("cvt.rn.bf16x2.f32 %0, %1, %2;" : "=r"(h) : "f"(x1), "f"(x0));
    float h0 = __uint_as_float(h << 16);
    float h1 = __uint_as_float(h & 0xffff0000u);
    float l0 = x0 - h0, l1 = x1 - h1;
    uint32_t l;
    asm("cvt.rn.bf16x2.f32 %0, %1, %2;" : "=r"(l) : "f"(l1), "f"(l0));
    hi = h; lo = l;
}
__device__ __forceinline__ void cp16(uint32_t dst, const void* src) {
    asm volatile("cp.async.cg.shared.global [%0], [%1], 16;" :: "r"(dst), "l"(src));
}

// SMEM layout per stage (bytes). 80B rows (32 bf16 + pad) and 272B trans rows
// are conflict-free per ldmatrix phase (20r mod 32 / 4r mod 32 bank starts).
#define RS     80
#define RS_T   272
#define OFF_AHI 0
#define OFF_ALO 10240
#define OFF_BHI 20480
#define OFF_BLO 30720
#define STAGE   40960
#define OFF_BIAS (2*STAGE)
#define SMEM_TOT (OFF_BIAS + 512)

// ===========================================================================
// cp.async issue of one 128x32 (bf16) hi/lo A-pair + B-pair
// ===========================================================================
template<int TRANSA>
__device__ __forceinline__ void issue_stage(uint32_t sb,
        const char* Ahi, const char* Alo, const char* Bhi, const char* Blo,
        int k0, int ldA, int ldB, int tid) {
#pragma unroll
    for (int p = 0; p < 2; ++p) {
        int i = p * 256 + tid;
        uint32_t dst; size_t so;
        if (TRANSA) {
            int r = i >> 4, c = (i & 15) * 16;                 // [k-row][m bytes]
            so  = ((size_t)(k0 + r) * ldA) * 2 + c;
            dst = sb + OFF_AHI + r * RS_T + c;
        } else {
            int r = i >> 2, c = (i & 3) * 16;                  // [m-row][k bytes]
            so  = ((size_t)r * ldA + k0) * 2 + c;
            dst = sb + OFF_AHI + r * RS + c;
        }
        cp16(dst, Ahi + so);
        cp16(dst + (OFF_ALO - OFF_AHI), Alo + so);
    }
#pragma unroll
    for (int p = 0; p < 2; ++p) {
        int i = p * 256 + tid;
        int r = i >> 2, c = (i & 3) * 16;
        size_t so = ((size_t)r * ldB + k0) * 2 + c;
        uint32_t dst = sb + OFF_BHI + r * RS + c;
        cp16(dst, Bhi + so);
        cp16(dst + (OFF_BLO - OFF_BHI), Blo + so);
    }
}

// ===========================================================================
// 3-term split-bf16 GEMM, pre-split operands:
//   C[b][m][n] = sum_k A[m][k]*B[n][k]  (+bias[n]); TRANSA: A stored [k][m]
// 128x128x32 tiles, 256 thr, warp 64x32, cp.async 2-stage, 2 CTAs/SM.
// ===========================================================================
template <int TRANSA, int BIAS, int OUTSPLIT>
__global__ void __launch_bounds__(256, 2)
mma3s_kernel(const __nv_bfloat16* __restrict__ Ahi_, const __nv_bfloat16* __restrict__ Alo_,
             const __nv_bfloat16* __restrict__ Bhi_, const __nv_bfloat16* __restrict__ Blo_,
             const float* __restrict__ bias, float* __restrict__ Cf,
             __nv_bfloat16* __restrict__ Chi, __nv_bfloat16* __restrict__ Clo,
             int K, int ldA, int ldB, int ldC,
             unsigned long long sA, unsigned long long sB, unsigned long long sC) {
    extern __shared__ __align__(128) char sm[];
    const uint32_t sbase = smem_u32(sm);
    const int tid = threadIdx.x, lane = tid & 31, wid = tid >> 5;
    const int wm = (wid & 1) * 64, wn = (wid >> 1) * 32;
    const int m0 = blockIdx.y * 128, n0 = blockIdx.x * 128, b = blockIdx.z;

    const char* Ahi = reinterpret_cast<const char*>(Ahi_) +
        (TRANSA ? ((size_t)b * sA + m0) * 2 : ((size_t)b * sA + (size_t)m0 * ldA) * 2);
    const char* Alo = reinterpret_cast<const char*>(Alo_) +
        (TRANSA ? ((size_t)b * sA + m0) * 2 : ((size_t)b * sA + (size_t)m0 * ldA) * 2);
    const char* Bhi = reinterpret_cast<const char*>(Bhi_) +
        ((size_t)b * sB + (size_t)n0 * ldB) * 2;
    const char* Blo = reinterpret_cast<const char*>(Blo_) +
        ((size_t)b * sB + (size_t)n0 * ldB) * 2;

    float* biasS = reinterpret_cast<float*>(sm + OFF_BIAS);
    if (BIAS && tid < 128) biasS[tid] = bias[n0 + tid];

    float acc[4][4][4];
#pragma unroll
    for (int i = 0; i < 4; ++i)
#pragma unroll
        for (int j = 0; j < 4; ++j)
#pragma unroll
            for (int v = 0; v < 4; ++v) acc[i][j][v] = 0.0f;

    const int aM_row = lane & 15;
    const int aM_col = (lane & 16) ? 8 : 0;
    const int aT_k   = (lane & 7) + ((lane & 16) ? 8 : 0);
    const int aT_m   = (lane & 8) ? 8 : 0;
    const int bN_row = (lane & 7) + ((lane & 16) ? 8 : 0);
    const int bN_col = (lane & 8) ? 8 : 0;

    const int nIter = K >> 5;
    issue_stage<TRANSA>(sbase, Ahi, Alo, Bhi, Blo, 0, ldA, ldB, tid);
    asm volatile("cp.async.commit_group;" ::: "memory");

    for (int ch = 0; ch < nIter; ++ch) {
        if (ch + 1 < nIter) {
            issue_stage<TRANSA>(sbase + ((ch + 1) & 1) * STAGE, Ahi, Alo, Bhi, Blo,
                                (ch + 1) * 32, ldA, ldB, tid);
            asm volatile("cp.async.commit_group;" ::: "memory");
            asm volatile("cp.async.wait_group 1;" ::: "memory");
        } else {
            asm volatile("cp.async.wait_group 0;" ::: "memory");
        }
        __syncthreads();

        const uint32_t sb = sbase + (ch & 1) * STAGE;
#pragma unroll
        for (int ks = 0; ks < 2; ++ks) {
            uint32_t Bh[2][4], Bl[2][4];
#pragma unroll
            for (int j = 0; j < 2; ++j) {
                uint32_t o = (uint32_t)(wn + j * 16 + bN_row) * RS +
                             (uint32_t)(ks * 16 + bN_col) * 2;
                ldsm4(Bh[j], sb + OFF_BHI + o);
                ldsm4(Bl[j], sb + OFF_BLO + o);
            }
#pragma unroll
            for (int mi = 0; mi < 4; ++mi) {
                uint32_t Ah[4], Al[4];
                if (TRANSA) {
                    uint32_t o = (uint32_t)(ks * 16 + aT_k) * RS_T +
                                 (uint32_t)(wm + mi * 16 + aT_m) * 2;
                    ldsm4t(Ah, sb + OFF_AHI + o);
                    ldsm4t(Al, sb + OFF_ALO + o);
                } else {
                    uint32_t o = (uint32_t)(wm + mi * 16 + aM_row) * RS +
                                 (uint32_t)(ks * 16 + aM_col) * 2;
                    ldsm4(Ah, sb + OFF_AHI + o);
                    ldsm4(Al, sb + OFF_ALO + o);
                }
#pragma unroll
                for (int nj = 0; nj < 4; ++nj) {
                    uint32_t bh0 = Bh[nj >> 1][(nj & 1) * 2];
                    uint32_t bh1 = Bh[nj >> 1][(nj & 1) * 2 + 1];
                    uint32_t bl0 = Bl[nj >> 1][(nj & 1) * 2];
                    uint32_t bl1 = Bl[nj >> 1][(nj & 1) * 2 + 1];
                    mma_bf16(acc[mi][nj], Ah, bh0, bh1);
                    mma_bf16(acc[mi][nj], Ah, bl0, bl1);
                    mma_bf16(acc[mi][nj], Al, bh0, bh1);
                }
            }
        }
        __syncthreads();   // all warps done with this buffer before it is refilled
    }

    const int q4 = lane >> 2, t4 = lane & 3;
#pragma unroll
    for (int mi = 0; mi < 4; ++mi) {
#pragma unroll
        for (int nj = 0; nj < 4; ++nj) {
            int r0 = wm + mi * 16 + q4;
            int c0 = wn + nj * 8 + t4 * 2;
            float b0 = BIAS ? biasS[c0] : 0.0f;
            float b1 = BIAS ? biasS[c0 + 1] : 0.0f;
            float v00 = acc[mi][nj][0] + b0, v01 = acc[mi][nj][1] + b1;
            float v10 = acc[mi][nj][2] + b0, v11 = acc[mi][nj][3] + b1;
            if (OUTSPLIT) {
                size_t e0 = (size_t)b * sC + (size_t)(m0 + r0) * ldC + n0 + c0;
                size_t e1 = (size_t)b * sC + (size_t)(m0 + r0 + 8) * ldC + n0 + c0;
                uint32_t h, l;
                split2(v00, v01, h, l);
                *reinterpret_cast<uint32_t*>(reinterpret_cast<char*>(Chi) + e0 * 2) = h;
                *reinterpret_cast<uint32_t*>(reinterpret_cast<char*>(Clo) + e0 * 2) = l;
                split2(v10, v11, h, l);
                *reinterpret_cast<uint32_t*>(reinterpret_cast<char*>(Chi) + e1 * 2) = h;
                *reinterpret_cast<uint32_t*>(reinterpret_cast<char*>(Clo) + e1 * 2) = l;
            } else {
                float* Cb = Cf + (size_t)b * sC + (size_t)(m0 + r0) * ldC + n0 + c0;
                *reinterpret_cast<float2*>(Cb) = make_float2(v00, v01);
                *reinterpret_cast<float2*>(Cb + (size_t)8 * ldC) = make_float2(v10, v11);
            }
        }
    }
}

// ===========================================================================
// fp32 -> bf16 hi/lo split pass (pure bandwidth)
// ===========================================================================
__global__ void split_kernel(const float* __restrict__ x, __nv_bfloat16* __restrict__ hi,
                             __nv_bfloat16* __restrict__ lo) {
    size_t i = (size_t)blockIdx.x * blockDim.x + threadIdx.x;
    float4 v = reinterpret_cast<const float4*>(x)[i];
    uint32_t h0, l0, h1, l1;
    split2(v.x, v.y, h0, l0);
    split2(v.z, v.w, h1, l1);
    reinterpret_cast<uint2*>(hi)[i] = make_uint2(h0, h1);
    reinterpret_cast<uint2*>(lo)[i] = make_uint2(l0, l1);
}

// ===========================================================================
// Copy query_features into concat first half
// ===========================================================================
__global__ void copy_first_half(const float* __restrict__ qf, float* __restrict__ out) {
    int idx = blockIdx.x * blockDim.x + threadIdx.x;
    const int perb = (CH * HW) / 4;
    int b = idx / perb;
    int r = idx - b * perb;
    reinterpret_cast<float4*>(out)[(size_t)b * (2 * CH * HW / 4) + r] =
        reinterpret_cast<const float4*>(qf)[idx];
}

// ===========================================================================
// Row softmax over 1024 entries; reads fp32 S, writes split bf16 P
// ===========================================================================
__global__ void softmax_rows() {
    int row = blockIdx.x;
    const float* r = g_S + (size_t)row * HW;
    int tid = threadIdx.x;
    __shared__ float red[8];

    float4 v = *reinterpret_cast<const float4*>(r + tid * 4);
    float m = fmaxf(fmaxf(v.x, v.y), fmaxf(v.z, v.w));
#pragma unroll
    for (int off = 16; off; off >>= 1) m = fmaxf(m, __shfl_xor_sync(0xffffffffu, m, off));
    if ((tid & 31) == 0) red[tid >> 5] = m;
    __syncthreads();
    float rowmax = red[0];
#pragma unroll
    for (int i = 1; i < 8; ++i) rowmax = fmaxf(rowmax, red[i]);

    v.x = __expf(v.x - rowmax);
    v.y = __expf(v.y - rowmax);
    v.z = __expf(v.z - rowmax);
    v.w = __expf(v.w - rowmax);
    float s = v.x + v.y + v.z + v.w;
#pragma unroll
    for (int off = 16; off; off >>= 1) s += __shfl_xor_sync(0xffffffffu, s, off);
    __syncthreads();
    if ((tid & 31) == 0) red[tid >> 5] = s;
    __syncthreads();
    float tot = red[0];
#pragma unroll
    for (int i = 1; i < 8; ++i) tot += red[i];
    float inv = 1.0f / tot;

    uint32_t h0, l0, h1, l1;
    split2(v.x * inv, v.y * inv, h0, l0);
    split2(v.z * inv, v.w * inv, h1, l1);
    size_t e = (size_t)row * HW + tid * 4;
    *reinterpret_cast<uint2*>(reinterpret_cast<char*>(g_PHi) + e * 2) = make_uint2(h0, h1);
    *reinterpret_cast<uint2*>(reinterpret_cast<char*>(g_PLo) + e * 2) = make_uint2(l0, l1);
}

// ===========================================================================
extern "C" void kernel_launch(void* const* d_in, const int* in_sizes, int n_in,
                              void* d_out, int out_size) {
    const float* qf   = (const float*)d_in[0];   // (16, 2048, 32, 32)
    const float* pf   = (const float*)d_in[1];   // (16, 2048, 32, 32)
    const float* Wm   = (const float*)d_in[2];   // (256, 2048)
    const float* bias = (const float*)d_in[3];   // (256,)
    float* out = (float*)d_out;                  // (16, 4096, 32, 32)

    cudaFuncSetAttribute(mma3s_kernel<1,1,1>, cudaFuncAttributeMaxDynamicSharedMemorySize, SMEM_TOT);
    cudaFuncSetAttribute(mma3s_kernel<0,0,0>, cudaFuncAttributeMaxDynamicSharedMemorySize, SMEM_TOT);

    __nv_bfloat16 *XqHi, *XqLo, *XpHi, *XpLo, *WHi, *WLo;
    __nv_bfloat16 *QHi, *QLo, *KHi, *KLo, *PHi, *PLo;
    float* S;
    cudaGetSymbolAddress((void**)&XqHi, g_XqHi); cudaGetSymbolAddress((void**)&XqLo, g_XqLo);
    cudaGetSymbolAddress((void**)&XpHi, g_XpHi); cudaGetSymbolAddress((void**)&XpLo, g_XpLo);
    cudaGetSymbolAddress((void**)&WHi,  g_WHi);  cudaGetSymbolAddress((void**)&WLo,  g_WLo);
    cudaGetSymbolAddress((void**)&QHi,  g_QHi);  cudaGetSymbolAddress((void**)&QLo,  g_QLo);
    cudaGetSymbolAddress((void**)&KHi,  g_KHi);  cudaGetSymbolAddress((void**)&KLo,  g_KLo);
    cudaGetSymbolAddress((void**)&PHi,  g_PHi);  cudaGetSymbolAddress((void**)&PLo,  g_PLo);
    cudaGetSymbolAddress((void**)&S,    g_S);

    copy_first_half<<<(BATCH * CH * HW / 4) / 256, 256>>>(qf, out);
    split_kernel<<<BATCH * CH * HW / 4 / 256, 256>>>(qf, XqHi, XqLo);
    split_kernel<<<BATCH * CH * HW / 4 / 256, 256>>>(pf, XpHi, XpLo);
    split_kernel<<<HID * CH / 4 / 256, 256>>>(Wm, WHi, WLo);

    // Projections: Qt[hw][o] = sum_c X[c][hw] * W[o][c]   (A trans, out split)
    dim3 gqk(HID / 128, HW / 128, BATCH);        // (2, 8, 16)
    mma3s_kernel<1,1,1><<<gqk, 256, SMEM_TOT>>>(XqHi, XqLo, WHi, WLo, bias,
        nullptr, QHi, QLo, CH, HW, CH, HID,
        (unsigned long long)CH * HW, 0ULL, (unsigned long long)HW * HID);
    mma3s_kernel<1,1,1><<<gqk, 256, SMEM_TOT>>>(XpHi, XpLo, WHi, WLo, bias,
        nullptr, KHi, KLo, CH, HW, CH, HID,
        (unsigned long long)CH * HW, 0ULL, (unsigned long long)HW * HID);

    // Scores: S[q][k2] = sum_o Qt[q][o] * Kt[k2][o]  -> fp32
    dim3 gs(HW / 128, HW / 128, BATCH);          // (8, 8, 16)
    mma3s_kernel<0,0,0><<<gs, 256, SMEM_TOT>>>(QHi, QLo, KHi, KLo, nullptr,
        S, nullptr, nullptr, HID, HID, HID, HW,
        (unsigned long long)HW * HID, (unsigned long long)HW * HID,
        (unsigned long long)HW * HW);

    softmax_rows<<<BATCH * HW, 256>>>();

    // AV: out2[c][q] = sum_k2 V[c][k2] * P[q][k2]  -> fp32 into concat 2nd half
    dim3 gav(HW / 128, CH / 128, BATCH);         // (8, 16, 16)
    mma3s_kernel<0,0,0><<<gav, 256, SMEM_TOT>>>(XpHi, XpLo, PHi, PLo, nullptr,
        out + (size_t)CH * HW, nullptr, nullptr, HW, HW, HW, HW,
        (unsigned long long)CH * HW, (unsigned long long)HW * HW,
        (unsigned long long)2 * CH * HW);
}

// round 5
// speedup vs baseline: 3.7842x; 1.3530x over previous
#include <cuda_runtime.h>
#include <cuda_fp16.h>
#include <cstdint>

#define BATCH 16
#define CH    2048
#define HID   256
#define HW    1024

// ---- pre-split fp16 operand storage + fp32 scores ----
__device__ __align__(128) __half g_XqHi[BATCH*CH*HW], g_XqLo[BATCH*CH*HW];
__device__ __align__(128) __half g_XpHi[BATCH*CH*HW], g_XpLo[BATCH*CH*HW];
__device__ __align__(128) __half g_WHi [HID*CH],      g_WLo [HID*CH];
__device__ __align__(128) __half g_QHi [BATCH*HW*HID], g_QLo[BATCH*HW*HID];
__device__ __align__(128) __half g_KHi [BATCH*HW*HID], g_KLo[BATCH*HW*HID];
__device__ __align__(128) __half g_PHi [BATCH*HW*HW];
__device__ __align__(128) float  g_S   [BATCH*HW*HW];

// ===========================================================================
// Helpers (base-target sm_80+ instructions only)
// ===========================================================================
__device__ __forceinline__ uint32_t smem_u32(const void* p) {
    uint32_t a;
    asm("{ .reg .u64 t; cvta.to.shared.u64 t, %1; cvt.u32.u64 %0, t; }" : "=r"(a) : "l"(p));
    return a;
}
__device__ __forceinline__ void ldsm4(uint32_t (&r)[4], uint32_t addr) {
    asm volatile("ldmatrix.sync.aligned.m8n8.x4.shared.b16 {%0,%1,%2,%3}, [%4];"
                 : "=r"(r[0]), "=r"(r[1]), "=r"(r[2]), "=r"(r[3]) : "r"(addr));
}
__device__ __forceinline__ void ldsm4t(uint32_t (&r)[4], uint32_t addr) {
    asm volatile("ldmatrix.sync.aligned.m8n8.x4.trans.shared.b16 {%0,%1,%2,%3}, [%4];"
                 : "=r"(r[0]), "=r"(r[1]), "=r"(r[2]), "=r"(r[3]) : "r"(addr));
}
__device__ __forceinline__ void mma_f16(float (&d)[4], const uint32_t (&a)[4],
                                        uint32_t b0, uint32_t b1) {
    asm volatile("mma.sync.aligned.m16n8k16.row.col.f32.f16.f16.f32 "
                 "{%0,%1,%2,%3}, {%4,%5,%6,%7}, {%8,%9}, {%0,%1,%2,%3};"
                 : "+f"(d[0]), "+f"(d[1]), "+f"(d[2]), "+f"(d[3])
                 : "r"(a[0]), "r"(a[1]), "r"(a[2]), "r"(a[3]), "r"(b0), "r"(b1));
}
// fp32 pair -> fp16 hi pair + fp16 lo pair (lo = x - hi, exact in fp16)
__device__ __forceinline__ void split2h(float x0, float x1, uint32_t& hi, uint32_t& lo) {
    uint32_t h;
    asm("cvt.rn.f16x2.f32 %0, %1, %2;" : "=r"(h) : "f"(x1), "f"(x0));
    __half2 hh = *reinterpret_cast<__half2*>(&h);
    float h0 = __low2float(hh), h1 = __high2float(hh);
    float l0 = x0 - h0, l1 = x1 - h1;
    uint32_t l;
    asm("cvt.rn.f16x2.f32 %0, %1, %2;" : "=r"(l) : "f"(l1), "f"(l0));
    hi = h; lo = l;
}
__device__ __forceinline__ uint32_t pack_h2(float x0, float x1) {
    uint32_t h;
    asm("cvt.rn.f16x2.f32 %0, %1, %2;" : "=r"(h) : "f"(x1), "f"(x0));
    return h;
}
__device__ __forceinline__ void cp16(uint32_t dst, const void* src) {
    asm volatile("cp.async.cg.shared.global [%0], [%1], 16;" :: "r"(dst), "l"(src));
}

// SMEM geometry: 80B rows (32 f16 + 16B pad) and 272B trans rows are
// conflict-free for every ldmatrix phase.
#define RS     80
#define RS_T   272

// ===========================================================================
// cp.async stage issue (skips lo operands when TERMS==1)
// ===========================================================================
template<int TRANSA, int TERMS>
__device__ __forceinline__ void issue_stage(uint32_t sb,
        const char* Ahi, const char* Alo, const char* Bhi, const char* Blo,
        int k0, int ldA, int ldB, int tid) {
    constexpr int ALOo = (TERMS == 3) ? 10240 : 0;
    constexpr int BHIo = (TERMS == 3) ? 20480 : 10240;
    constexpr int BLOo = (TERMS == 3) ? 30720 : 10240;
#pragma unroll
    for (int p = 0; p < 2; ++p) {
        int i = p * 256 + tid;
        uint32_t dst; size_t so;
        if (TRANSA) {
            int r = i >> 4, c = (i & 15) * 16;
            so  = ((size_t)(k0 + r) * ldA) * 2 + c;
            dst = sb + r * RS_T + c;
        } else {
            int r = i >> 2, c = (i & 3) * 16;
            so  = ((size_t)r * ldA + k0) * 2 + c;
            dst = sb + r * RS + c;
        }
        cp16(dst, Ahi + so);
        if (TERMS == 3) cp16(dst + ALOo, Alo + so);
    }
#pragma unroll
    for (int p = 0; p < 2; ++p) {
        int i = p * 256 + tid;
        int r = i >> 2, c = (i & 3) * 16;
        size_t so = ((size_t)r * ldB + k0) * 2 + c;
        uint32_t dst = sb + BHIo + r * RS + c;
        cp16(dst, Bhi + so);
        if (TERMS == 3) cp16(dst + (BLOo - BHIo), Blo + so);
    }
}

// ===========================================================================
// Split-fp16 GEMM: C[b][m][n] = sum_k A[m][k]*B[n][k] (+bias[n])
// TERMS=3: Ahi*Bhi + Ahi*Blo + Alo*Bhi ; TERMS=1: Ahi*Bhi only.
// Terms are issued as separate full sweeps of the 16 acc tiles so no
// accumulator sees back-to-back dependent HMMAs.
// 128x128x32 tiles, 256 thr, warp 64x32, cp.async double buffer.
// ===========================================================================
template <int TRANSA, int BIAS, int TERMS, int OUTSPLIT>
__global__ void __launch_bounds__(256)
mma3s_kernel(const __half* __restrict__ Ahi_, const __half* __restrict__ Alo_,
             const __half* __restrict__ Bhi_, const __half* __restrict__ Blo_,
             const float* __restrict__ bias, float* __restrict__ Cf,
             __half* __restrict__ Chi, __half* __restrict__ Clo,
             int K, int ldA, int ldB, int ldC,
             unsigned long long sA, unsigned long long sB, unsigned long long sC) {
    constexpr int ALOo = (TERMS == 3) ? 10240 : 0;
    constexpr int BHIo = (TERMS == 3) ? 20480 : 10240;
    constexpr int BLOo = (TERMS == 3) ? 30720 : 10240;
    constexpr int STG  = (TERMS == 3) ? 40960 : 20480;

    extern __shared__ __align__(128) char sm[];
    const uint32_t sbase = smem_u32(sm);
    const int tid = threadIdx.x, lane = tid & 31, wid = tid >> 5;
    const int wm = (wid & 1) * 64, wn = (wid >> 1) * 32;
    const int m0 = blockIdx.y * 128, n0 = blockIdx.x * 128, b = blockIdx.z;

    const size_t aOff = TRANSA ? ((size_t)b * sA + m0) * 2
                               : ((size_t)b * sA + (size_t)m0 * ldA) * 2;
    const char* Ahi = reinterpret_cast<const char*>(Ahi_) + aOff;
    const char* Alo = (TERMS == 3) ? reinterpret_cast<const char*>(Alo_) + aOff : nullptr;
    const size_t bOff = ((size_t)b * sB + (size_t)n0 * ldB) * 2;
    const char* Bhi = reinterpret_cast<const char*>(Bhi_) + bOff;
    const char* Blo = (TERMS == 3) ? reinterpret_cast<const char*>(Blo_) + bOff : nullptr;

    float* biasS = reinterpret_cast<float*>(sm + 2 * STG);
    if (BIAS && tid < 128) biasS[tid] = bias[n0 + tid];

    float acc[4][4][4];
#pragma unroll
    for (int i = 0; i < 4; ++i)
#pragma unroll
        for (int j = 0; j < 4; ++j)
#pragma unroll
            for (int v = 0; v < 4; ++v) acc[i][j][v] = 0.0f;

    const int aM_row = lane & 15;
    const int aM_col = (lane & 16) ? 8 : 0;
    const int aT_k   = (lane & 7) + ((lane & 16) ? 8 : 0);
    const int aT_m   = (lane & 8) ? 8 : 0;
    const int bN_row = (lane & 7) + ((lane & 16) ? 8 : 0);
    const int bN_col = (lane & 8) ? 8 : 0;

    const int nIter = K >> 5;
    issue_stage<TRANSA, TERMS>(sbase, Ahi, Alo, Bhi, Blo, 0, ldA, ldB, tid);
    asm volatile("cp.async.commit_group;" ::: "memory");

    for (int ch = 0; ch < nIter; ++ch) {
        if (ch + 1 < nIter) {
            issue_stage<TRANSA, TERMS>(sbase + ((ch + 1) & 1) * STG, Ahi, Alo, Bhi, Blo,
                                       (ch + 1) * 32, ldA, ldB, tid);
            asm volatile("cp.async.commit_group;" ::: "memory");
            asm volatile("cp.async.wait_group 1;" ::: "memory");
        } else {
            asm volatile("cp.async.wait_group 0;" ::: "memory");
        }
        __syncthreads();

        const uint32_t sb = sbase + (ch & 1) * STG;
#pragma unroll
        for (int ks = 0; ks < 2; ++ks) {
            uint32_t Ah[4][4], Al[4][4], Bh[2][4], Bl[2][4];
#pragma unroll
            for (int j = 0; j < 2; ++j) {
                uint32_t o = (uint32_t)(wn + j * 16 + bN_row) * RS +
                             (uint32_t)(ks * 16 + bN_col) * 2;
                ldsm4(Bh[j], sb + BHIo + o);
                if (TERMS == 3) ldsm4(Bl[j], sb + BLOo + o);
            }
#pragma unroll
            for (int mi = 0; mi < 4; ++mi) {
                if (TRANSA) {
                    uint32_t o = (uint32_t)(ks * 16 + aT_k) * RS_T +
                                 (uint32_t)(wm + mi * 16 + aT_m) * 2;
                    ldsm4t(Ah[mi], sb + o);
                    if (TERMS == 3) ldsm4t(Al[mi], sb + ALOo + o);
                } else {
                    uint32_t o = (uint32_t)(wm + mi * 16 + aM_row) * RS +
                                 (uint32_t)(ks * 16 + aM_col) * 2;
                    ldsm4(Ah[mi], sb + o);
                    if (TERMS == 3) ldsm4(Al[mi], sb + ALOo + o);
                }
            }
            // term 1: hi*hi — 16 independent accumulators per sweep
#pragma unroll
            for (int mi = 0; mi < 4; ++mi)
#pragma unroll
                for (int nj = 0; nj < 4; ++nj)
                    mma_f16(acc[mi][nj], Ah[mi],
                            Bh[nj >> 1][(nj & 1) * 2], Bh[nj >> 1][(nj & 1) * 2 + 1]);
            if (TERMS == 3) {
                // term 2: hi*lo
#pragma unroll
                for (int mi = 0; mi < 4; ++mi)
#pragma unroll
                    for (int nj = 0; nj < 4; ++nj)
                        mma_f16(acc[mi][nj], Ah[mi],
                                Bl[nj >> 1][(nj & 1) * 2], Bl[nj >> 1][(nj & 1) * 2 + 1]);
                // term 3: lo*hi
#pragma unroll
                for (int mi = 0; mi < 4; ++mi)
#pragma unroll
                    for (int nj = 0; nj < 4; ++nj)
                        mma_f16(acc[mi][nj], Al[mi],
                                Bh[nj >> 1][(nj & 1) * 2], Bh[nj >> 1][(nj & 1) * 2 + 1]);
            }
        }
        __syncthreads();
    }

    const int q4 = lane >> 2, t4 = lane & 3;
#pragma unroll
    for (int mi = 0; mi < 4; ++mi) {
#pragma unroll
        for (int nj = 0; nj < 4; ++nj) {
            int r0 = wm + mi * 16 + q4;
            int c0 = wn + nj * 8 + t4 * 2;
            float b0 = BIAS ? biasS[c0] : 0.0f;
            float b1 = BIAS ? biasS[c0 + 1] : 0.0f;
            float v00 = acc[mi][nj][0] + b0, v01 = acc[mi][nj][1] + b1;
            float v10 = acc[mi][nj][2] + b0, v11 = acc[mi][nj][3] + b1;
            if (OUTSPLIT) {
                size_t e0 = (size_t)b * sC + (size_t)(m0 + r0) * ldC + n0 + c0;
                size_t e1 = (size_t)b * sC + (size_t)(m0 + r0 + 8) * ldC + n0 + c0;
                uint32_t h, l;
                split2h(v00, v01, h, l);
                *reinterpret_cast<uint32_t*>(reinterpret_cast<char*>(Chi) + e0 * 2) = h;
                *reinterpret_cast<uint32_t*>(reinterpret_cast<char*>(Clo) + e0 * 2) = l;
                split2h(v10, v11, h, l);
                *reinterpret_cast<uint32_t*>(reinterpret_cast<char*>(Chi) + e1 * 2) = h;
                *reinterpret_cast<uint32_t*>(reinterpret_cast<char*>(Clo) + e1 * 2) = l;
            } else {
                float* Cb = Cf + (size_t)b * sC + (size_t)(m0 + r0) * ldC + n0 + c0;
                *reinterpret_cast<float2*>(Cb) = make_float2(v00, v01);
                *reinterpret_cast<float2*>(Cb + (size_t)8 * ldC) = make_float2(v10, v11);
            }
        }
    }
}

// ===========================================================================
// Split passes. split_copy also writes the concat first half (fused copy).
// ===========================================================================
__global__ void split_copy_kernel(const float* __restrict__ x, __half* __restrict__ hi,
                                  __half* __restrict__ lo, float* __restrict__ out) {
    size_t i = (size_t)blockIdx.x * blockDim.x + threadIdx.x;
    float4 v = reinterpret_cast<const float4*>(x)[i];
    const int perb = (CH * HW) / 4;
    int b = (int)(i / perb);
    int r = (int)(i - (size_t)b * perb);
    reinterpret_cast<float4*>(out)[(size_t)b * (2 * CH * HW / 4) + r] = v;
    uint32_t h0, l0, h1, l1;
    split2h(v.x, v.y, h0, l0);
    split2h(v.z, v.w, h1, l1);
    reinterpret_cast<uint2*>(hi)[i] = make_uint2(h0, h1);
    reinterpret_cast<uint2*>(lo)[i] = make_uint2(l0, l1);
}
__global__ void split_kernel(const float* __restrict__ x, __half* __restrict__ hi,
                             __half* __restrict__ lo) {
    size_t i = (size_t)blockIdx.x * blockDim.x + threadIdx.x;
    float4 v = reinterpret_cast<const float4*>(x)[i];
    uint32_t h0, l0, h1, l1;
    split2h(v.x, v.y, h0, l0);
    split2h(v.z, v.w, h1, l1);
    reinterpret_cast<uint2*>(hi)[i] = make_uint2(h0, h1);
    reinterpret_cast<uint2*>(lo)[i] = make_uint2(l0, l1);
}

// ===========================================================================
// Row softmax over 1024 fp32 scores; writes fp16 probs (hi only)
// ===========================================================================
__global__ void softmax_rows() {
    int row = blockIdx.x;
    const float* r = g_S + (size_t)row * HW;
    int tid = threadIdx.x;
    __shared__ float red[8];

    float4 v = *reinterpret_cast<const float4*>(r + tid * 4);
    float m = fmaxf(fmaxf(v.x, v.y), fmaxf(v.z, v.w));
#pragma unroll
    for (int off = 16; off; off >>= 1) m = fmaxf(m, __shfl_xor_sync(0xffffffffu, m, off));
    if ((tid & 31) == 0) red[tid >> 5] = m;
    __syncthreads();
    float rowmax = red[0];
#pragma unroll
    for (int i = 1; i < 8; ++i) rowmax = fmaxf(rowmax, red[i]);

    v.x = __expf(v.x - rowmax);
    v.y = __expf(v.y - rowmax);
    v.z = __expf(v.z - rowmax);
    v.w = __expf(v.w - rowmax);
    float s = v.x + v.y + v.z + v.w;
#pragma unroll
    for (int off = 16; off; off >>= 1) s += __shfl_xor_sync(0xffffffffu, s, off);
    __syncthreads();
    if ((tid & 31) == 0) red[tid >> 5] = s;
    __syncthreads();
    float tot = red[0];
#pragma unroll
    for (int i = 1; i < 8; ++i) tot += red[i];
    float inv = 1.0f / tot;

    uint32_t h0 = pack_h2(v.x * inv, v.y * inv);
    uint32_t h1 = pack_h2(v.z * inv, v.w * inv);
    size_t e = (size_t)row * HW + tid * 4;
    *reinterpret_cast<uint2*>(reinterpret_cast<char*>(g_PHi) + e * 2) = make_uint2(h0, h1);
}

// ===========================================================================
extern "C" void kernel_launch(void* const* d_in, const int* in_sizes, int n_in,
                              void* d_out, int out_size) {
    const float* qf   = (const float*)d_in[0];
    const float* pf   = (const float*)d_in[1];
    const float* Wm   = (const float*)d_in[2];
    const float* bias = (const float*)d_in[3];
    float* out = (float*)d_out;

    const int SMEM3 = 2 * 40960 + 512;
    const int SMEM1 = 2 * 20480 + 512;
    cudaFuncSetAttribute(mma3s_kernel<1,1,3,1>, cudaFuncAttributeMaxDynamicSharedMemorySize, SMEM3);
    cudaFuncSetAttribute(mma3s_kernel<0,0,3,0>, cudaFuncAttributeMaxDynamicSharedMemorySize, SMEM3);
    cudaFuncSetAttribute(mma3s_kernel<0,0,1,0>, cudaFuncAttributeMaxDynamicSharedMemorySize, SMEM1);

    __half *XqHi, *XqLo, *XpHi, *XpLo, *WHi, *WLo;
    __half *QHi, *QLo, *KHi, *KLo, *PHi;
    float* S;
    cudaGetSymbolAddress((void**)&XqHi, g_XqHi); cudaGetSymbolAddress((void**)&XqLo, g_XqLo);
    cudaGetSymbolAddress((void**)&XpHi, g_XpHi); cudaGetSymbolAddress((void**)&XpLo, g_XpLo);
    cudaGetSymbolAddress((void**)&WHi,  g_WHi);  cudaGetSymbolAddress((void**)&WLo,  g_WLo);
    cudaGetSymbolAddress((void**)&QHi,  g_QHi);  cudaGetSymbolAddress((void**)&QLo,  g_QLo);
    cudaGetSymbolAddress((void**)&KHi,  g_KHi);  cudaGetSymbolAddress((void**)&KLo,  g_KLo);
    cudaGetSymbolAddress((void**)&PHi,  g_PHi);
    cudaGetSymbolAddress((void**)&S,    g_S);

    split_copy_kernel<<<BATCH * CH * HW / 4 / 256, 256>>>(qf, XqHi, XqLo, out);
    split_kernel<<<BATCH * CH * HW / 4 / 256, 256>>>(pf, XpHi, XpLo);
    split_kernel<<<HID * CH / 4 / 256, 256>>>(Wm, WHi, WLo);

    // Projections: Qt[hw][o] = sum_c X[c][hw] * W[o][c]  (A trans, split fp16 out)
    dim3 gqk(HID / 128, HW / 128, BATCH);
    mma3s_kernel<1,1,3,1><<<gqk, 256, SMEM3>>>(XqHi, XqLo, WHi, WLo, bias,
        nullptr, QHi, QLo, CH, HW, CH, HID,
        (unsigned long long)CH * HW, 0ULL, (unsigned long long)HW * HID);
    mma3s_kernel<1,1,3,1><<<gqk, 256, SMEM3>>>(XpHi, XpLo, WHi, WLo, bias,
        nullptr, KHi, KLo, CH, HW, CH, HID,
        (unsigned long long)CH * HW, 0ULL, (unsigned long long)HW * HID);

    // Scores: fp32 out
    dim3 gs(HW / 128, HW / 128, BATCH);
    mma3s_kernel<0,0,3,0><<<gs, 256, SMEM3>>>(QHi, QLo, KHi, KLo, nullptr,
        S, nullptr, nullptr, HID, HID, HID, HW,
        (unsigned long long)HW * HID, (unsigned long long)HW * HID,
        (unsigned long long)HW * HW);

    softmax_rows<<<BATCH * HW, 256>>>();

    // AV single-term: out2[c][q] = sum_k V[c][k] * P[q][k]
    dim3 gav(HW / 128, CH / 128, BATCH);
    mma3s_kernel<0,0,1,0><<<gav, 256, SMEM1>>>(XpHi, nullptr, PHi, nullptr, nullptr,
        out + (size_t)CH * HW, nullptr, nullptr, HW, HW, HW, HW,
        (unsigned long long)CH * HW, (unsigned long long)HW * HW,
        (unsigned long long)2 * CH * HW);
}